// round 1
// baseline (speedup 1.0000x reference)
#include <cuda_runtime.h>
#include <cuda_fp16.h>
#include <cuda_fp8.h>
#include <cstdint>
#include <cstddef>

#define MDIM 65536
#define KDIM 512
#define NDIM 512

// ---------------- device scratch (static: no runtime allocation) ----------------
__device__ unsigned g_ax_bits;
__device__ unsigned g_aw_bits;
__device__ float g_xscale, g_wscale, g_oscale;
__device__ __align__(16) __half g_xq[(size_t)MDIM * KDIM];   // 64 MB
__device__ __align__(16) __half g_wq[(size_t)NDIM * KDIM];   // 512 KB (w^T quantized)

// ---------------- init ----------------
__global__ void k_init() { g_ax_bits = 0u; g_aw_bits = 0u; }

// ---------------- amax reduction (positive floats compare as uints) ----------------
__global__ void k_amax(const float4* __restrict__ p, int n4, int which) {
    float m = 0.0f;
    for (int i = blockIdx.x * blockDim.x + threadIdx.x; i < n4;
         i += gridDim.x * blockDim.x) {
        float4 v = p[i];
        m = fmaxf(m, fmaxf(fmaxf(fabsf(v.x), fabsf(v.y)),
                           fmaxf(fabsf(v.z), fabsf(v.w))));
    }
#pragma unroll
    for (int o = 16; o; o >>= 1) m = fmaxf(m, __shfl_xor_sync(0xffffffffu, m, o));
    __shared__ float sm[8];
    if ((threadIdx.x & 31) == 0) sm[threadIdx.x >> 5] = m;
    __syncthreads();
    if (threadIdx.x < 8) {
        m = sm[threadIdx.x];
#pragma unroll
        for (int o = 4; o; o >>= 1) m = fmaxf(m, __shfl_xor_sync(0xffu, m, o));
        if (threadIdx.x == 0)
            atomicMax(which ? &g_aw_bits : &g_ax_bits, __float_as_uint(m));
    }
}

// ---------------- scales (exactly as reference computes them) ----------------
__global__ void k_scale() {
    float ax = fmaxf(__uint_as_float(g_ax_bits), 1e-12f);
    float aw = fmaxf(__uint_as_float(g_aw_bits), 1e-12f);
    float xs = 448.0f / ax;
    float ws = 448.0f / aw;
    g_xscale = xs;
    g_wscale = ws;
    g_oscale = (1.0f / xs) * (1.0f / ws);
}

// ---------------- quantization: f32 -> e4m3 (RN, satfinite) -> half (exact) ----------------
__device__ __forceinline__ __half q_e4m3(float v, float s) {
    float q = fminf(fmaxf(v * s, -448.0f), 448.0f);
    __nv_fp8_storage_t r = __nv_cvt_float_to_fp8(q, __NV_SATFINITE, __NV_E4M3);
    __half_raw hr = __nv_cvt_fp8_to_halfraw(r, __NV_E4M3);
    return *reinterpret_cast<__half*>(&hr);
}

__global__ void k_quant_x(const float4* __restrict__ x, int n4) {
    float s = g_xscale;
    for (int i = blockIdx.x * blockDim.x + threadIdx.x; i < n4;
         i += gridDim.x * blockDim.x) {
        float4 v = x[i];
        __half2 h01 = __halves2half2(q_e4m3(v.x, s), q_e4m3(v.y, s));
        __half2 h23 = __halves2half2(q_e4m3(v.z, s), q_e4m3(v.w, s));
        uint2 u;
        u.x = *reinterpret_cast<unsigned*>(&h01);
        u.y = *reinterpret_cast<unsigned*>(&h23);
        reinterpret_cast<uint2*>(g_xq)[i] = u;
    }
}

// weight is [K][N]; store transposed [N][K] so both GEMM operands are K-major
__global__ void k_quant_w(const float* __restrict__ w) {
    int idx = blockIdx.x * blockDim.x + threadIdx.x;  // 0 .. K*N-1
    float s = g_wscale;
    int k = idx >> 9;        // KDIM=512
    int n = idx & 511;
    g_wq[(size_t)n * KDIM + k] = q_e4m3(w[idx], s);
}

// ---------------- GEMM: [M,K] x [N,K]^T -> [M,N], fp16 HMMA, f32 accum ----------------
#define BM 128
#define BN 128
#define BK 32
#define KS 40   // padded smem row stride (halfs): 80 B, 16B-aligned, conflict-light

__device__ __forceinline__ void cp16(uint32_t dst, const void* src) {
    asm volatile("cp.async.cg.shared.global [%0], [%1], 16;" ::"r"(dst), "l"(src));
}
__device__ __forceinline__ void ldm4(uint32_t* r, uint32_t addr) {
    asm volatile("ldmatrix.sync.aligned.m8n8.x4.shared.b16 {%0,%1,%2,%3}, [%4];"
                 : "=r"(r[0]), "=r"(r[1]), "=r"(r[2]), "=r"(r[3])
                 : "r"(addr));
}
__device__ __forceinline__ void mma16816(float* d, const uint32_t* a, const uint32_t* b) {
    asm volatile(
        "mma.sync.aligned.m16n8k16.row.col.f32.f16.f16.f32 "
        "{%0,%1,%2,%3}, {%4,%5,%6,%7}, {%8,%9}, {%0,%1,%2,%3};"
        : "+f"(d[0]), "+f"(d[1]), "+f"(d[2]), "+f"(d[3])
        : "r"(a[0]), "r"(a[1]), "r"(a[2]), "r"(a[3]), "r"(b[0]), "r"(b[1]));
}

__global__ void __launch_bounds__(256)
k_gemm(float* __restrict__ C) {
    __shared__ __half sA[2][BM * KS];
    __shared__ __half sB[2][BN * KS];

    const int tid  = threadIdx.x;
    const int lane = tid & 31;
    const int warp = tid >> 5;
    const int wm = warp & 3;   // m offset = wm*32
    const int wn = warp >> 2;  // n offset = wn*64

    const int m0 = blockIdx.y * BM;
    const int n0 = blockIdx.x * BN;

    const uint32_t sA_base = (uint32_t)__cvta_generic_to_shared(&sA[0][0]);
    const uint32_t sB_base = (uint32_t)__cvta_generic_to_shared(&sB[0][0]);

    const int lrow = tid >> 2;         // 0..63
    const int lcol = (tid & 3) << 3;   // 0,8,16,24 halfs (16B chunks)

    float acc[2][8][4];
#pragma unroll
    for (int a = 0; a < 2; a++)
#pragma unroll
        for (int b = 0; b < 8; b++)
#pragma unroll
            for (int c = 0; c < 4; c++) acc[a][b][c] = 0.0f;

    auto load_tiles = [&](int kt, int bufi) {
        const int k0 = kt * BK;
#pragma unroll
        for (int h = 0; h < 2; h++) {
            int r = lrow + h * 64;
            cp16(sA_base + (uint32_t)(bufi * BM * KS + r * KS + lcol) * 2,
                 &g_xq[(size_t)(m0 + r) * KDIM + k0 + lcol]);
            cp16(sB_base + (uint32_t)(bufi * BN * KS + r * KS + lcol) * 2,
                 &g_wq[(size_t)(n0 + r) * KDIM + k0 + lcol]);
        }
    };

    load_tiles(0, 0);
    asm volatile("cp.async.commit_group;");

    const int NKT = KDIM / BK;  // 16
    int buf = 0;

    // ldmatrix per-lane address pattern (tiles: [r0 k0][r8 k0][r0 k8][r8 k8])
    const int lm_row = ((lane >> 3) & 1) * 8 + (lane & 7);
    const int lm_col = (lane >> 4) << 3;

    for (int kt = 0; kt < NKT; kt++) {
        asm volatile("cp.async.wait_group 0;");
        __syncthreads();
        if (kt + 1 < NKT) {
            load_tiles(kt + 1, buf ^ 1);
            asm volatile("cp.async.commit_group;");
        }

#pragma unroll
        for (int ks = 0; ks < BK; ks += 16) {
            uint32_t af[2][4];
#pragma unroll
            for (int im = 0; im < 2; im++) {
                int r = wm * 32 + im * 16 + lm_row;
                int c = ks + lm_col;
                ldm4(af[im], sA_base + (uint32_t)(buf * BM * KS + r * KS + c) * 2);
            }
            uint32_t bf[8][2];
#pragma unroll
            for (int ib = 0; ib < 4; ib++) {
                int r = wn * 64 + ib * 16 + lm_row;
                int c = ks + lm_col;
                uint32_t t[4];
                ldm4(t, sB_base + (uint32_t)(buf * BN * KS + r * KS + c) * 2);
                bf[2 * ib][0] = t[0];
                bf[2 * ib + 1][0] = t[1];
                bf[2 * ib][1] = t[2];
                bf[2 * ib + 1][1] = t[3];
            }
#pragma unroll
            for (int im = 0; im < 2; im++)
#pragma unroll
                for (int in = 0; in < 8; in++)
                    mma16816(acc[im][in], af[im], bf[in]);
        }
        buf ^= 1;
    }

    const float s = g_oscale;
    const int rb = m0 + wm * 32 + (lane >> 2);
    const int cb = n0 + wn * 64 + ((lane & 3) << 1);
#pragma unroll
    for (int im = 0; im < 2; im++) {
#pragma unroll
        for (int in = 0; in < 8; in++) {
            int r = rb + im * 16;
            int c = cb + in * 8;
            float2 v0 = make_float2(acc[im][in][0] * s, acc[im][in][1] * s);
            float2 v1 = make_float2(acc[im][in][2] * s, acc[im][in][3] * s);
            *reinterpret_cast<float2*>(&C[(size_t)r * NDIM + c]) = v0;
            *reinterpret_cast<float2*>(&C[(size_t)(r + 8) * NDIM + c]) = v1;
        }
    }
}

// ---------------- launch ----------------
extern "C" void kernel_launch(void* const* d_in, const int* in_sizes, int n_in,
                              void* d_out, int out_size) {
    const float* x = (const float*)d_in[0];   // [8,8192,512] f32
    const float* w = (const float*)d_in[1];   // [512,512] f32
    float* out = (float*)d_out;               // [65536,512] f32

    k_init<<<1, 1>>>();
    k_amax<<<1024, 256>>>((const float4*)x, (MDIM * KDIM) / 4, 0);
    k_amax<<<64, 256>>>((const float4*)w, (KDIM * NDIM) / 4, 1);
    k_scale<<<1, 1>>>();
    k_quant_x<<<4096, 256>>>((const float4*)x, (MDIM * KDIM) / 4);
    k_quant_w<<<(KDIM * NDIM) / 256, 256>>>(w);
    k_gemm<<<dim3(NDIM / BN, MDIM / BM), 256>>>(out);
}

// round 5
// speedup vs baseline: 1.0971x; 1.0971x over previous
#include <cuda_runtime.h>
#include <cuda_fp16.h>
#include <cuda_fp8.h>
#include <cstdint>
#include <cstddef>

#define MDIM 65536
#define KDIM 512
#define NDIM 512

// ---------------- device scratch ----------------
__device__ float g_part[1088];                 // per-block amax partials (1024 x, 64 w)
__device__ float g_xscale, g_wscale, g_oscale;
__device__ __align__(16) uint8_t g_xq8[(size_t)MDIM * KDIM];   // 32 MB fp8
__device__ __align__(16) uint8_t g_wq8[(size_t)NDIM * KDIM];   // 256 KB fp8 (w^T)

// ---------------- fused amax: blocks [0,1024) -> x, [1024,1088) -> w ----------------
__global__ void k_amax_all(const float4* __restrict__ x, const float4* __restrict__ w) {
    float m = 0.0f;
    if (blockIdx.x < 1024) {
        const int n4 = (MDIM * KDIM) / 4;
        for (int i = blockIdx.x * 256 + threadIdx.x; i < n4; i += 1024 * 256) {
            float4 v = x[i];
            m = fmaxf(m, fmaxf(fmaxf(fabsf(v.x), fabsf(v.y)),
                               fmaxf(fabsf(v.z), fabsf(v.w))));
        }
    } else {
        const int n4 = (KDIM * NDIM) / 4;
        for (int i = (blockIdx.x - 1024) * 256 + threadIdx.x; i < n4; i += 64 * 256) {
            float4 v = w[i];
            m = fmaxf(m, fmaxf(fmaxf(fabsf(v.x), fabsf(v.y)),
                               fmaxf(fabsf(v.z), fabsf(v.w))));
        }
    }
#pragma unroll
    for (int o = 16; o; o >>= 1) m = fmaxf(m, __shfl_xor_sync(0xffffffffu, m, o));
    __shared__ float sm[8];
    if ((threadIdx.x & 31) == 0) sm[threadIdx.x >> 5] = m;
    __syncthreads();
    if (threadIdx.x < 8) {
        m = sm[threadIdx.x];
#pragma unroll
        for (int o = 4; o; o >>= 1) m = fmaxf(m, __shfl_xor_sync(0xffu, m, o));
        if (threadIdx.x == 0) g_part[blockIdx.x] = m;
    }
}

// ---------------- reduce partials + compute scales (1 block, 1024 threads) ------------
__global__ void k_scale_reduce() {
    const int tid = threadIdx.x;
    float vx = g_part[tid];
    float vw = (tid < 64) ? g_part[1024 + tid] : 0.0f;
#pragma unroll
    for (int o = 16; o; o >>= 1) {
        vx = fmaxf(vx, __shfl_xor_sync(0xffffffffu, vx, o));
        vw = fmaxf(vw, __shfl_xor_sync(0xffffffffu, vw, o));
    }
    __shared__ float sx[32], sw[32];
    if ((tid & 31) == 0) { sx[tid >> 5] = vx; sw[tid >> 5] = vw; }
    __syncthreads();
    if (tid < 32) {
        vx = sx[tid];
        vw = sw[tid];
#pragma unroll
        for (int o = 16; o; o >>= 1) {
            vx = fmaxf(vx, __shfl_xor_sync(0xffffffffu, vx, o));
            vw = fmaxf(vw, __shfl_xor_sync(0xffffffffu, vw, o));
        }
        if (tid == 0) {
            float xs = 448.0f / fmaxf(vx, 1e-12f);
            float ws = 448.0f / fmaxf(vw, 1e-12f);
            g_xscale = xs;
            g_wscale = ws;
            g_oscale = (1.0f / xs) * (1.0f / ws);
        }
    }
}

// ---------------- quantize f32 -> e4m3 (RN satfinite), matching reference -------------
__device__ __forceinline__ uint8_t q8(float v, float s) {
    float q = fminf(fmaxf(v * s, -448.0f), 448.0f);
    return (uint8_t)__nv_cvt_float_to_fp8(q, __NV_SATFINITE, __NV_E4M3);
}

// blocks [0,4096) -> x (fp8, same layout); [4096,4160) -> w^T (fp8, [N][K])
__global__ void k_quant_all(const float4* __restrict__ x, const float* __restrict__ w) {
    if (blockIdx.x < 4096) {
        const float s = g_xscale;
        const int n4 = (MDIM * KDIM) / 4;
        for (int i = blockIdx.x * 256 + threadIdx.x; i < n4; i += 4096 * 256) {
            float4 v = x[i];
            uchar4 u;
            u.x = q8(v.x, s); u.y = q8(v.y, s); u.z = q8(v.z, s); u.w = q8(v.w, s);
            reinterpret_cast<uchar4*>(g_xq8)[i] = u;
        }
    } else {
        const float s = g_wscale;
        const int bi = blockIdx.x - 4096;  // 0..63
#pragma unroll
        for (int j = 0; j < 16; j++) {
            int idx = bi * 4096 + j * 256 + threadIdx.x;  // over K*N, k-major
            int k = idx >> 9;
            int n = idx & 511;
            g_wq8[(size_t)n * KDIM + k] = q8(w[idx], s);
        }
    }
}

// ================= FP8 mma.sync GEMM: [M,K] x [N,K]^T -> [M,N] ====================
#define BM 128
#define BN 256
#define BKB 64              // K bytes per stage (64 fp8)
#define KS8 80              // padded smem row stride in bytes (conflict-free ldmatrix)
#define ASTG (BM * KS8)     // 10240
#define BSTG (BN * KS8)     // 20480
#define GEMM_SMEM (2 * (ASTG + BSTG))  // 61440

__device__ __forceinline__ void cp16(uint32_t dst, const void* src) {
    asm volatile("cp.async.cg.shared.global [%0], [%1], 16;" ::"r"(dst), "l"(src));
}
__device__ __forceinline__ void ldm4(uint32_t* r, uint32_t addr) {
    asm volatile("ldmatrix.sync.aligned.m8n8.x4.shared.b16 {%0,%1,%2,%3}, [%4];"
                 : "=r"(r[0]), "=r"(r[1]), "=r"(r[2]), "=r"(r[3])
                 : "r"(addr));
}
__device__ __forceinline__ void mma_e4m3(float* d, const uint32_t* a, const uint32_t* b) {
    asm volatile(
        "mma.sync.aligned.m16n8k32.row.col.f32.e4m3.e4m3.f32 "
        "{%0,%1,%2,%3}, {%4,%5,%6,%7}, {%8,%9}, {%0,%1,%2,%3};"
        : "+f"(d[0]), "+f"(d[1]), "+f"(d[2]), "+f"(d[3])
        : "r"(a[0]), "r"(a[1]), "r"(a[2]), "r"(a[3]), "r"(b[0]), "r"(b[1]));
}

__global__ void __launch_bounds__(512, 1) k_gemm(float* __restrict__ C) {
    extern __shared__ uint8_t smem[];
    // layout: A[2][ASTG] then B[2][BSTG]
    const uint32_t sA_base = (uint32_t)__cvta_generic_to_shared(smem);
    const uint32_t sB_base = sA_base + 2 * ASTG;

    const int tid = threadIdx.x;
    const int lane = tid & 31;
    const int warp = tid >> 5;     // 0..15
    const int wm = warp & 3;       // m offset wm*32
    const int wn = warp >> 2;      // n offset wn*64

    const int m0 = blockIdx.y * BM;
    const int n0 = blockIdx.x * BN;

    float acc[2][8][4];
#pragma unroll
    for (int a = 0; a < 2; a++)
#pragma unroll
        for (int b = 0; b < 8; b++)
#pragma unroll
            for (int c = 0; c < 4; c++) acc[a][b][c] = 0.0f;

    // loader: 512 threads; A = 512 x 16B chunks (1/thread), B = 1024 (2/thread)
    const int arow = tid >> 2;          // 0..127
    const int akc  = (tid & 3) << 4;    // 0,16,32,48 byte offset in K
    auto load_tiles = [&](int kt, int bufi) {
        const int k0 = kt * BKB;
        cp16(sA_base + bufi * ASTG + arow * KS8 + akc,
             &g_xq8[(size_t)(m0 + arow) * KDIM + k0 + akc]);
#pragma unroll
        for (int j = 0; j < 2; j++) {
            int c = tid + j * 512;
            int row = c >> 2, kc = (c & 3) << 4;
            cp16(sB_base + bufi * BSTG + row * KS8 + kc,
                 &g_wq8[(size_t)(n0 + row) * KDIM + k0 + kc]);
        }
    };

    load_tiles(0, 0);
    asm volatile("cp.async.commit_group;");

    const int NKT = KDIM / BKB;  // 8
    const int lm_row = ((lane >> 3) & 1) * 8 + (lane & 7);
    const int lm_colB = (lane >> 4) << 4;   // byte offset 0 or 16

    for (int kt = 0; kt < NKT; kt++) {
        const int buf = kt & 1;
        asm volatile("cp.async.wait_group 0;");
        __syncthreads();
        if (kt + 1 < NKT) {
            load_tiles(kt + 1, buf ^ 1);
            asm volatile("cp.async.commit_group;");
        }

#pragma unroll
        for (int ks = 0; ks < 2; ks++) {          // two k32 steps per 64B stage
            uint32_t af[2][4];
#pragma unroll
            for (int im = 0; im < 2; im++) {
                int r = wm * 32 + im * 16 + lm_row;
                ldm4(af[im], sA_base + buf * ASTG + r * KS8 + ks * 32 + lm_colB);
            }
            uint32_t bf[8][2];
#pragma unroll
            for (int ib = 0; ib < 4; ib++) {
                int r = wn * 64 + ib * 16 + lm_row;
                uint32_t t[4];
                ldm4(t, sB_base + buf * BSTG + r * KS8 + ks * 32 + lm_colB);
                bf[2 * ib][0]     = t[0];
                bf[2 * ib + 1][0] = t[1];
                bf[2 * ib][1]     = t[2];
                bf[2 * ib + 1][1] = t[3];
            }
#pragma unroll
            for (int im = 0; im < 2; im++)
#pragma unroll
                for (int in = 0; in < 8; in++)
                    mma_e4m3(acc[im][in], af[im], bf[in]);
        }
    }

    const float s = g_oscale;
    const int rb = m0 + wm * 32 + (lane >> 2);
    const int cb = n0 + wn * 64 + ((lane & 3) << 1);
#pragma unroll
    for (int im = 0; im < 2; im++) {
#pragma unroll
        for (int in = 0; in < 8; in++) {
            int r = rb + im * 16;
            int c = cb + in * 8;
            float2 v0 = make_float2(acc[im][in][0] * s, acc[im][in][1] * s);
            float2 v1 = make_float2(acc[im][in][2] * s, acc[im][in][3] * s);
            *reinterpret_cast<float2*>(&C[(size_t)r * NDIM + c]) = v0;
            *reinterpret_cast<float2*>(&C[(size_t)(r + 8) * NDIM + c]) = v1;
        }
    }
}

// ---------------- launch ----------------
extern "C" void kernel_launch(void* const* d_in, const int* in_sizes, int n_in,
                              void* d_out, int out_size) {
    const float* x = (const float*)d_in[0];   // [8,8192,512] f32
    const float* w = (const float*)d_in[1];   // [512,512] f32
    float* out = (float*)d_out;               // [65536,512] f32

    cudaFuncSetAttribute(k_gemm, cudaFuncAttributeMaxDynamicSharedMemorySize,
                         GEMM_SMEM);

    k_amax_all<<<1088, 256>>>((const float4*)x, (const float4*)w);
    k_scale_reduce<<<1, 1024>>>();
    k_quant_all<<<4160, 256>>>((const float4*)x, w);
    k_gemm<<<dim3(NDIM / BN, MDIM / BM), 512, GEMM_SMEM>>>(out);
}

// round 6
// speedup vs baseline: 1.1307x; 1.0306x over previous
#include <cuda_runtime.h>
#include <cuda_fp16.h>
#include <cuda_fp8.h>
#include <cstdint>
#include <cstddef>

#define MDIM 65536
#define KDIM 512
#define NDIM 512

// ---------------- device scratch ----------------
__device__ float g_part[1088];                 // per-block amax partials (1024 x, 64 w)
__device__ float g_xscale, g_wscale, g_oscale;
__device__ __align__(16) uint8_t g_xq8[(size_t)MDIM * KDIM];   // 32 MB fp8
__device__ __align__(16) uint8_t g_wq8[(size_t)NDIM * KDIM];   // 256 KB fp8 (w^T)

// ---------------- fused amax: blocks [0,1024) -> x, [1024,1088) -> w ----------------
__global__ void k_amax_all(const float4* __restrict__ x, const float4* __restrict__ w) {
    float m = 0.0f;
    if (blockIdx.x < 1024) {
        const int n4 = (MDIM * KDIM) / 4;
        for (int i = blockIdx.x * 256 + threadIdx.x; i < n4; i += 1024 * 256) {
            float4 v = x[i];
            m = fmaxf(m, fmaxf(fmaxf(fabsf(v.x), fabsf(v.y)),
                               fmaxf(fabsf(v.z), fabsf(v.w))));
        }
    } else {
        const int n4 = (KDIM * NDIM) / 4;
        for (int i = (blockIdx.x - 1024) * 256 + threadIdx.x; i < n4; i += 64 * 256) {
            float4 v = w[i];
            m = fmaxf(m, fmaxf(fmaxf(fabsf(v.x), fabsf(v.y)),
                               fmaxf(fabsf(v.z), fabsf(v.w))));
        }
    }
#pragma unroll
    for (int o = 16; o; o >>= 1) m = fmaxf(m, __shfl_xor_sync(0xffffffffu, m, o));
    __shared__ float sm[8];
    if ((threadIdx.x & 31) == 0) sm[threadIdx.x >> 5] = m;
    __syncthreads();
    if (threadIdx.x < 8) {
        m = sm[threadIdx.x];
#pragma unroll
        for (int o = 4; o; o >>= 1) m = fmaxf(m, __shfl_xor_sync(0xffu, m, o));
        if (threadIdx.x == 0) g_part[blockIdx.x] = m;
    }
}

// ---------------- reduce partials + compute scales (1 block, 1024 threads) ------------
__global__ void k_scale_reduce() {
    const int tid = threadIdx.x;
    float vx = g_part[tid];
    float vw = (tid < 64) ? g_part[1024 + tid] : 0.0f;
#pragma unroll
    for (int o = 16; o; o >>= 1) {
        vx = fmaxf(vx, __shfl_xor_sync(0xffffffffu, vx, o));
        vw = fmaxf(vw, __shfl_xor_sync(0xffffffffu, vw, o));
    }
    __shared__ float sx[32], sw[32];
    if ((tid & 31) == 0) { sx[tid >> 5] = vx; sw[tid >> 5] = vw; }
    __syncthreads();
    if (tid < 32) {
        vx = sx[tid];
        vw = sw[tid];
#pragma unroll
        for (int o = 16; o; o >>= 1) {
            vx = fmaxf(vx, __shfl_xor_sync(0xffffffffu, vx, o));
            vw = fmaxf(vw, __shfl_xor_sync(0xffffffffu, vw, o));
        }
        if (tid == 0) {
            float xs = 448.0f / fmaxf(vx, 1e-12f);
            float ws = 448.0f / fmaxf(vw, 1e-12f);
            g_xscale = xs;
            g_wscale = ws;
            g_oscale = (1.0f / xs) * (1.0f / ws);
        }
    }
}

// ---------------- quantize f32 -> e4m3 (RN satfinite), matching reference -------------
__device__ __forceinline__ uint8_t q8(float v, float s) {
    float q = fminf(fmaxf(v * s, -448.0f), 448.0f);
    return (uint8_t)__nv_cvt_float_to_fp8(q, __NV_SATFINITE, __NV_E4M3);
}

// blocks [0,4096) -> x (fp8, same layout); [4096,4160) -> w^T (fp8, [N][K])
__global__ void k_quant_all(const float4* __restrict__ x, const float* __restrict__ w) {
    if (blockIdx.x < 4096) {
        const float s = g_xscale;
        const int n4 = (MDIM * KDIM) / 4;
        for (int i = blockIdx.x * 256 + threadIdx.x; i < n4; i += 4096 * 256) {
            float4 v = x[i];
            uchar4 u;
            u.x = q8(v.x, s); u.y = q8(v.y, s); u.z = q8(v.z, s); u.w = q8(v.w, s);
            reinterpret_cast<uchar4*>(g_xq8)[i] = u;
        }
    } else {
        const float s = g_wscale;
        const int bi = blockIdx.x - 4096;  // 0..63
#pragma unroll
        for (int j = 0; j < 16; j++) {
            int idx = bi * 4096 + j * 256 + threadIdx.x;  // over K*N, k-major
            int k = idx >> 9;
            int n = idx & 511;
            g_wq8[(size_t)n * KDIM + k] = q8(w[idx], s);
        }
    }
}

// ================= FP8 mma.sync GEMM: [M,K] x [N,K]^T -> [M,N] ====================
#define BM 128
#define BN 256
#define BKB 64              // K bytes per stage (64 fp8)
#define NS 4                // pipeline depth
#define KS8 80              // padded smem row stride in bytes (conflict-free ldmatrix)
#define ASTG (BM * KS8)     // 10240
#define BSTG (BN * KS8)     // 20480
#define GEMM_SMEM (NS * (ASTG + BSTG))  // 122880

__device__ __forceinline__ void cp16(uint32_t dst, const void* src) {
    asm volatile("cp.async.cg.shared.global [%0], [%1], 16;" ::"r"(dst), "l"(src));
}
__device__ __forceinline__ void ldm4(uint32_t* r, uint32_t addr) {
    asm volatile("ldmatrix.sync.aligned.m8n8.x4.shared.b16 {%0,%1,%2,%3}, [%4];"
                 : "=r"(r[0]), "=r"(r[1]), "=r"(r[2]), "=r"(r[3])
                 : "r"(addr));
}
__device__ __forceinline__ void mma_e4m3(float* d, const uint32_t* a, const uint32_t* b) {
    asm volatile(
        "mma.sync.aligned.m16n8k32.row.col.f32.e4m3.e4m3.f32 "
        "{%0,%1,%2,%3}, {%4,%5,%6,%7}, {%8,%9}, {%0,%1,%2,%3};"
        : "+f"(d[0]), "+f"(d[1]), "+f"(d[2]), "+f"(d[3])
        : "r"(a[0]), "r"(a[1]), "r"(a[2]), "r"(a[3]), "r"(b[0]), "r"(b[1]));
}

__global__ void __launch_bounds__(512, 1) k_gemm(float* __restrict__ C) {
    extern __shared__ uint8_t smem[];
    const uint32_t sA_base = (uint32_t)__cvta_generic_to_shared(smem);
    const uint32_t sB_base = sA_base + NS * ASTG;

    const int tid = threadIdx.x;
    const int lane = tid & 31;
    const int warp = tid >> 5;     // 0..15
    const int wm = warp & 3;       // m offset wm*32
    const int wn = warp >> 2;      // n offset wn*64

    const int m0 = blockIdx.y * BM;
    const int n0 = blockIdx.x * BN;

    float acc[2][8][4];
#pragma unroll
    for (int a = 0; a < 2; a++)
#pragma unroll
        for (int b = 0; b < 8; b++)
#pragma unroll
            for (int c = 0; c < 4; c++) acc[a][b][c] = 0.0f;

    // ---- precomputed loader bases (stage/kt offsets are compile-time constants) ----
    const int arow = tid >> 2;              // 0..127
    const int akc  = (tid & 3) << 4;        // 0,16,32,48
    const uint8_t* gA = g_xq8 + (size_t)(m0 + arow) * KDIM + akc;
    const uint32_t sAdst = sA_base + arow * KS8 + akc;
    const int brow = tid >> 2;              // 0..127 (plus +128 row in 2nd cp)
    const int bkc  = (tid & 3) << 4;
    const uint8_t* gB0 = g_wq8 + (size_t)(n0 + brow) * KDIM + bkc;
    const uint8_t* gB1 = g_wq8 + (size_t)(n0 + brow + 128) * KDIM + bkc;
    const uint32_t sBdst0 = sB_base + brow * KS8 + bkc;
    const uint32_t sBdst1 = sB_base + (brow + 128) * KS8 + bkc;

#define LOADSTAGE(KT)                                                          \
    do {                                                                       \
        const int _s = (KT) & (NS - 1);                                        \
        cp16(sAdst + _s * ASTG, gA + (KT) * BKB);                              \
        cp16(sBdst0 + _s * BSTG, gB0 + (KT) * BKB);                            \
        cp16(sBdst1 + _s * BSTG, gB1 + (KT) * BKB);                            \
        asm volatile("cp.async.commit_group;");                                \
    } while (0)

    // ---- precomputed fragment bases ----
    const int lm_row = ((lane >> 3) & 1) * 8 + (lane & 7);
    const int lm_colB = (lane >> 4) << 4;   // 0 or 16 bytes
    const uint32_t aFragBase = sA_base + (wm * 32 + lm_row) * KS8 + lm_colB;
    const uint32_t bFragBase = sB_base + (wn * 64 + lm_row) * KS8 + lm_colB;

#define COMPUTESTAGE(KT)                                                       \
    do {                                                                       \
        const int _s = (KT) & (NS - 1);                                        \
        const uint32_t _ab = aFragBase + _s * ASTG;                            \
        const uint32_t _bb = bFragBase + _s * BSTG;                            \
        _Pragma("unroll") for (int ks = 0; ks < 2; ks++) {                     \
            uint32_t af[2][4];                                                 \
            ldm4(af[0], _ab + ks * 32);                                        \
            ldm4(af[1], _ab + 16 * KS8 + ks * 32);                             \
            uint32_t bf[8][2];                                                 \
            _Pragma("unroll") for (int ib = 0; ib < 4; ib++) {                 \
                uint32_t t[4];                                                 \
                ldm4(t, _bb + ib * 16 * KS8 + ks * 32);                        \
                bf[2 * ib][0] = t[0];                                          \
                bf[2 * ib + 1][0] = t[1];                                      \
                bf[2 * ib][1] = t[2];                                          \
                bf[2 * ib + 1][1] = t[3];                                      \
            }                                                                  \
            _Pragma("unroll") for (int im = 0; im < 2; im++)                   \
                _Pragma("unroll") for (int in = 0; in < 8; in++)               \
                    mma_e4m3(acc[im][in], af[im], bf[in]);                     \
        }                                                                      \
    } while (0)

#define WAITG(N) asm volatile("cp.async.wait_group %0;" ::"n"(N))

    // prologue: stages 0..2 in flight
    LOADSTAGE(0);
    LOADSTAGE(1);
    LOADSTAGE(2);

    // 8 K-iterations, hand-unrolled with exact wait depths
#define ITER(KT, WN)                                                           \
    do {                                                                       \
        WAITG(WN);                                                             \
        __syncthreads();                                                       \
        if ((KT) + 3 < 8) LOADSTAGE((KT) + 3);                                 \
        COMPUTESTAGE(KT);                                                      \
    } while (0)

    ITER(0, 2);
    ITER(1, 2);
    ITER(2, 2);
    ITER(3, 2);
    ITER(4, 2);
    ITER(5, 2);
    ITER(6, 1);
    ITER(7, 0);

#undef ITER
#undef WAITG
#undef COMPUTESTAGE
#undef LOADSTAGE

    const float s = g_oscale;
    const int rb = m0 + wm * 32 + (lane >> 2);
    const int cb = n0 + wn * 64 + ((lane & 3) << 1);
#pragma unroll
    for (int im = 0; im < 2; im++) {
#pragma unroll
        for (int in = 0; in < 8; in++) {
            int r = rb + im * 16;
            int c = cb + in * 8;
            float2 v0 = make_float2(acc[im][in][0] * s, acc[im][in][1] * s);
            float2 v1 = make_float2(acc[im][in][2] * s, acc[im][in][3] * s);
            *reinterpret_cast<float2*>(&C[(size_t)r * NDIM + c]) = v0;
            *reinterpret_cast<float2*>(&C[(size_t)(r + 8) * NDIM + c]) = v1;
        }
    }
}

// ---------------- launch ----------------
extern "C" void kernel_launch(void* const* d_in, const int* in_sizes, int n_in,
                              void* d_out, int out_size) {
    const float* x = (const float*)d_in[0];   // [8,8192,512] f32
    const float* w = (const float*)d_in[1];   // [512,512] f32
    float* out = (float*)d_out;               // [65536,512] f32

    cudaFuncSetAttribute(k_gemm, cudaFuncAttributeMaxDynamicSharedMemorySize,
                         GEMM_SMEM);

    k_amax_all<<<1088, 256>>>((const float4*)x, (const float4*)w);
    k_scale_reduce<<<1, 1024>>>();
    k_quant_all<<<4160, 256>>>((const float4*)x, w);
    k_gemm<<<dim3(NDIM / BN, MDIM / BM), 512, GEMM_SMEM>>>(out);
}